// round 11
// baseline (speedup 1.0000x reference)
#include <cuda_runtime.h>
#include <math_constants.h>
#include <cstdint>

// Problem constants
#define N_ROWS 262144
#define DIMK   512
#define DIMV   512

#define BLOCKS         304               // 2 per SM
#define CONS_WARPS     16
#define TPB            (32 * (CONS_WARPS + 1))       // 544: 16 consumer warps + 1 producer warp
#define ROWS_PER_STAGE CONS_WARPS        // one row per consumer warp per stage
#define STAGE_BYTES    (ROWS_PER_STAGE * DIMK * 4)   // 32 KB
#define NSTAGES        3                 // 96 KB dynamic smem
#define TOTAL_STAGES   (N_ROWS / ROWS_PER_STAGE)     // 16384
#define BASE_STAGES    (TOTAL_STAGES / BLOCKS)       // 53
#define EXTRA_STAGES   (TOTAL_STAGES % BLOCKS)       // 272

// Scratch: per-BLOCK online-softmax partials + completion ticket
__device__ float g_bmax[BLOCKS];
__device__ float g_bsum[BLOCKS];
__device__ int   g_barg[BLOCKS];
__device__ int   g_ticket = 0;           // reset by last block -> graph-replay safe

__device__ __forceinline__ uint32_t smem_u32(const void* p) {
    return (uint32_t)__cvta_generic_to_shared(p);
}

#define MBAR_INIT(addr, cnt) \
    asm volatile("mbarrier.init.shared.b64 [%0], %1;" :: "r"(addr), "r"(cnt) : "memory")
#define MBAR_EXPECT_TX(addr, tx) \
    asm volatile("mbarrier.arrive.expect_tx.shared.b64 _, [%0], %1;" :: "r"(addr), "r"(tx) : "memory")
#define MBAR_ARRIVE(addr) \
    asm volatile("mbarrier.arrive.shared.b64 _, [%0];" :: "r"(addr) : "memory")
#define BULK_G2S(dst, src, bytes, mbar) \
    asm volatile("cp.async.bulk.shared::cta.global.mbarrier::complete_tx::bytes [%0], [%1], %2, [%3];" \
                 :: "r"(dst), "l"(src), "r"(bytes), "r"(mbar) : "memory")

__device__ __forceinline__ void mbar_wait_parity(uint32_t mbar, uint32_t parity) {
    uint32_t done;
    asm volatile(
        "{\n\t.reg .pred p;\n\t"
        "mbarrier.try_wait.parity.acquire.cta.shared::cta.b64 p, [%1], %2;\n\t"
        "selp.b32 %0, 1, 0, p;\n\t}"
        : "=r"(done) : "r"(mbar), "r"(parity) : "memory");
    if (!done) {
        asm volatile(
            "{\n\t.reg .pred P1;\n\t"
            "WAIT_LOOP_%=:\n\t"
            "mbarrier.try_wait.parity.acquire.cta.shared::cta.b64 P1, [%0], %1, 0x989680;\n\t"
            "@P1 bra.uni WAIT_DONE_%=;\n\t"
            "bra.uni WAIT_LOOP_%=;\n\t"
            "WAIT_DONE_%=:\n\t}"
            :: "r"(mbar), "r"(parity) : "memory");
    }
}

// Online softmax combine
__device__ __forceinline__ void osm_merge(float& m, float& s, int& arg,
                                          float m2, float s2, int a2) {
    float nm = fmaxf(m, m2);
    s = s * __expf(m - nm) + s2 * __expf(m2 - nm);
    if (m2 > m) arg = a2;
    m = nm;
}

__global__ __launch_bounds__(TPB, 2)
void fused_kernel(const float* __restrict__ keys,
                  const float* __restrict__ query,
                  const float* __restrict__ values,
                  float* __restrict__ out) {
    extern __shared__ __align__(128) unsigned char stage_mem[];   // NSTAGES * 32 KB
    __shared__ __align__(8) unsigned long long full_bar[NSTAGES];
    __shared__ __align__(8) unsigned long long empty_bar[NSTAGES];
    __shared__ float sm_m[CONS_WARPS];
    __shared__ float sm_s[CONS_WARPS];
    __shared__ int   sm_a[CONS_WARPS];
    __shared__ bool  is_last;
    __shared__ int   s_best;
    __shared__ float s_inv;

    const int tid  = threadIdx.x;
    const int lane = tid & 31;
    const int wid  = tid >> 5;

    const uint32_t smem_base = smem_u32(stage_mem);
    const uint32_t fbar0 = smem_u32(&full_bar[0]);
    const uint32_t ebar0 = smem_u32(&empty_bar[0]);

    if (tid == 0) {
        #pragma unroll
        for (int j = 0; j < NSTAGES; j++) {
            MBAR_INIT(fbar0 + 8u * j, 1);           // tx-based completion
            MBAR_INIT(ebar0 + 8u * j, CONS_WARPS);  // one arrive per consumer warp
        }
    }
    __syncthreads();

    // Contiguous stage range for this block
    const int b    = blockIdx.x;
    const int sbeg = b * BASE_STAGES + min(b, EXTRA_STAGES);
    const int scnt = BASE_STAGES + (b < EXTRA_STAGES ? 1 : 0);

    if (wid == CONS_WARPS) {
        // ---------------- Producer warp ----------------
        if (lane == 0) {
            int pslot = 0;
            uint32_t pphase = 1;   // fresh barriers: first NSTAGES empty-waits pass immediately
            #pragma unroll 1
            for (int i = 0; i < scnt; i++) {
                mbar_wait_parity(ebar0 + 8u * pslot, pphase);
                MBAR_EXPECT_TX(fbar0 + 8u * pslot, (uint32_t)STAGE_BYTES);
                BULK_G2S(smem_base + (uint32_t)pslot * STAGE_BYTES,
                         keys + (size_t)(sbeg + i) * ROWS_PER_STAGE * DIMK,
                         (uint32_t)STAGE_BYTES, fbar0 + 8u * pslot);
                if (++pslot == NSTAGES) { pslot = 0; pphase ^= 1u; }
            }
        }
    } else {
        // ---------------- Consumer warps (free-running) ----------------
        const float4* q4 = (const float4*)query;
        const float4 q0 = q4[lane];
        const float4 q1 = q4[lane + 32];
        const float4 q2 = q4[lane + 64];
        const float4 q3 = q4[lane + 96];

        float m = -CUDART_INF_F;
        float s = 0.0f;
        int   arg = 0;

        int cslot = 0;
        uint32_t cphase = 0;

        #pragma unroll 1
        for (int i = 0; i < scnt; i++) {
            mbar_wait_parity(fbar0 + 8u * cslot, cphase);

            const int row = (sbeg + i) * ROWS_PER_STAGE + wid;
            const float4* st = (const float4*)(stage_mem + (size_t)cslot * STAGE_BYTES
                                               + (size_t)wid * (DIMK * 4));
            float4 a  = st[lane];
            float4 bb = st[lane + 32];
            float4 c  = st[lane + 64];
            float4 d  = st[lane + 96];
            float acc;
            acc  = a.x * q0.x; acc = fmaf(a.y, q0.y, acc); acc = fmaf(a.z, q0.z, acc); acc = fmaf(a.w, q0.w, acc);
            acc  = fmaf(bb.x, q1.x, acc); acc = fmaf(bb.y, q1.y, acc); acc = fmaf(bb.z, q1.z, acc); acc = fmaf(bb.w, q1.w, acc);
            acc  = fmaf(c.x, q2.x, acc); acc = fmaf(c.y, q2.y, acc); acc = fmaf(c.z, q2.z, acc); acc = fmaf(c.w, q2.w, acc);
            acc  = fmaf(d.x, q3.x, acc); acc = fmaf(d.y, q3.y, acc); acc = fmaf(d.z, q3.z, acc); acc = fmaf(d.w, q3.w, acc);

            #pragma unroll
            for (int off = 16; off > 0; off >>= 1)
                acc += __shfl_xor_sync(0xffffffffu, acc, off);

            {
                float nm = fmaxf(m, acc);
                s = s * __expf(m - nm) + __expf(acc - nm);
                if (acc > m) arg = row;
                m = nm;
            }

            __syncwarp();
            if (lane == 0) MBAR_ARRIVE(ebar0 + 8u * cslot);   // this warp is done with the slot

            if (++cslot == NSTAGES) { cslot = 0; cphase ^= 1u; }
        }

        if (lane == 0) {
            sm_m[wid] = m; sm_s[wid] = s; sm_a[wid] = arg;
        }
    }

    __syncthreads();

    // ---- Block-level merge of 16 consumer-warp partials ----
    if (tid == 0) {
        float bm = sm_m[0], bs = sm_s[0];
        int   ba = sm_a[0];
        #pragma unroll
        for (int w = 1; w < CONS_WARPS; w++)
            osm_merge(bm, bs, ba, sm_m[w], sm_s[w], sm_a[w]);
        g_bmax[b] = bm;
        g_bsum[b] = bs;
        g_barg[b] = ba;
        __threadfence();
        int old = atomicAdd(&g_ticket, 1);
        is_last = (old == BLOCKS - 1);
    }
    __syncthreads();

    if (!is_last) return;

    // ---- Last block: warp 0 merges 304 block partials (lean tail) ----
    if (wid == 0) {
        float lm = -CUDART_INF_F, ls = 0.0f;
        int   la = 0;
        #pragma unroll 1
        for (int i = lane; i < BLOCKS; i += 32)
            osm_merge(lm, ls, la, g_bmax[i], g_bsum[i], g_barg[i]);

        #pragma unroll
        for (int off = 16; off > 0; off >>= 1) {
            float m2 = __shfl_xor_sync(0xffffffffu, lm, off);
            float s2 = __shfl_xor_sync(0xffffffffu, ls, off);
            int   a2 = __shfl_xor_sync(0xffffffffu, la, off);
            float nm = fmaxf(lm, m2);
            ls = ls * __expf(lm - nm) + s2 * __expf(m2 - nm);
            if (m2 > lm) la = a2;
            lm = nm;
        }

        if (lane == 0) {
            s_best = la;
            s_inv  = 1.0f / ls;
            g_ticket = 0;   // reset for next graph replay
        }
    }
    __syncthreads();

    if (tid < DIMV) {
        out[tid] = values[(size_t)s_best * DIMV + tid] * s_inv;
    }
}

extern "C" void kernel_launch(void* const* d_in, const int* in_sizes, int n_in,
                              void* d_out, int out_size) {
    const float* query  = (const float*)d_in[0];
    const float* keys   = (const float*)d_in[1];
    const float* values = (const float*)d_in[2];
    float* out = (float*)d_out;

    cudaFuncSetAttribute(fused_kernel,
                         cudaFuncAttributeMaxDynamicSharedMemorySize,
                         NSTAGES * STAGE_BYTES);
    fused_kernel<<<BLOCKS, TPB, NSTAGES * STAGE_BYTES>>>(keys, query, values, out);
}

// round 15
// speedup vs baseline: 1.0080x; 1.0080x over previous
#include <cuda_runtime.h>
#include <math_constants.h>
#include <cstdint>

// Problem constants
#define N_ROWS 262144
#define DIMK   512
#define DIMV   512

#define BLOCKS         304               // 2 per SM
#define CONS_WARPS     16
#define TPB            (32 * (CONS_WARPS + 1))       // 544
#define ROWS_PER_STAGE CONS_WARPS        // one row per consumer warp per stage
#define STAGE_BYTES    (ROWS_PER_STAGE * DIMK * 4)   // 32 KB
#define NSTAGES        3                 // 96 KB dynamic smem
#define TOTAL_STAGES   (N_ROWS / ROWS_PER_STAGE)     // 16384

// Scratch: per-BLOCK partials, completion ticket, work-steal cursor
__device__ float g_bmax[BLOCKS];
__device__ float g_bsum[BLOCKS];
__device__ int   g_barg[BLOCKS];
__device__ int   g_ticket = 0;           // reset by last block -> graph-replay safe
__device__ int   g_next   = 0;           // stage steal cursor; reset by last block

__device__ __forceinline__ uint32_t smem_u32(const void* p) {
    return (uint32_t)__cvta_generic_to_shared(p);
}

#define MBAR_INIT(addr, cnt) \
    asm volatile("mbarrier.init.shared.b64 [%0], %1;" :: "r"(addr), "r"(cnt) : "memory")
#define MBAR_EXPECT_TX(addr, tx) \
    asm volatile("mbarrier.arrive.expect_tx.shared.b64 _, [%0], %1;" :: "r"(addr), "r"(tx) : "memory")
#define MBAR_ARRIVE(addr) \
    asm volatile("mbarrier.arrive.shared.b64 _, [%0];" :: "r"(addr) : "memory")
#define BULK_G2S(dst, src, bytes, mbar) \
    asm volatile("cp.async.bulk.shared::cta.global.mbarrier::complete_tx::bytes [%0], [%1], %2, [%3];" \
                 :: "r"(dst), "l"(src), "r"(bytes), "r"(mbar) : "memory")

__device__ __forceinline__ void mbar_wait_parity(uint32_t mbar, uint32_t parity) {
    uint32_t done;
    asm volatile(
        "{\n\t.reg .pred p;\n\t"
        "mbarrier.try_wait.parity.acquire.cta.shared::cta.b64 p, [%1], %2;\n\t"
        "selp.b32 %0, 1, 0, p;\n\t}"
        : "=r"(done) : "r"(mbar), "r"(parity) : "memory");
    if (!done) {
        asm volatile(
            "{\n\t.reg .pred P1;\n\t"
            "WAIT_LOOP_%=:\n\t"
            "mbarrier.try_wait.parity.acquire.cta.shared::cta.b64 P1, [%0], %1, 0x989680;\n\t"
            "@P1 bra.uni WAIT_DONE_%=;\n\t"
            "bra.uni WAIT_LOOP_%=;\n\t"
            "WAIT_DONE_%=:\n\t}"
            :: "r"(mbar), "r"(parity) : "memory");
    }
}

// Online softmax combine
__device__ __forceinline__ void osm_merge(float& m, float& s, int& arg,
                                          float m2, float s2, int a2) {
    float nm = fmaxf(m, m2);
    s = s * __expf(m - nm) + s2 * __expf(m2 - nm);
    if (m2 > m) arg = a2;
    m = nm;
}

__global__ __launch_bounds__(TPB, 2)
void fused_kernel(const float* __restrict__ keys,
                  const float* __restrict__ query,
                  const float* __restrict__ values,
                  float* __restrict__ out) {
    extern __shared__ __align__(128) unsigned char stage_mem[];   // NSTAGES * 32 KB
    __shared__ __align__(8) unsigned long long full_bar[NSTAGES];
    __shared__ __align__(8) unsigned long long empty_bar[NSTAGES];
    __shared__ int   s_rowbase[NSTAGES];   // row base per slot; -1 = sentinel
    __shared__ float sm_m[CONS_WARPS];
    __shared__ float sm_s[CONS_WARPS];
    __shared__ int   sm_a[CONS_WARPS];
    __shared__ bool  is_last;
    __shared__ int   s_best;
    __shared__ float s_inv;

    const int tid  = threadIdx.x;
    const int lane = tid & 31;
    const int wid  = tid >> 5;

    const uint32_t smem_base = smem_u32(stage_mem);
    const uint32_t fbar0 = smem_u32(&full_bar[0]);
    const uint32_t ebar0 = smem_u32(&empty_bar[0]);

    if (tid == 0) {
        #pragma unroll
        for (int j = 0; j < NSTAGES; j++) {
            MBAR_INIT(fbar0 + 8u * j, 1);           // tx-based completion (or sentinel arrive)
            MBAR_INIT(ebar0 + 8u * j, CONS_WARPS);  // one arrive per consumer warp
        }
    }
    __syncthreads();

    const int b = blockIdx.x;

    if (wid == CONS_WARPS) {
        // ---------------- Producer warp: dynamic work stealing ----------------
        if (lane == 0) {
            int pslot = 0;
            uint32_t pphase = 1;   // fresh barriers: first NSTAGES empty-waits pass immediately
            for (;;) {
                int idx = atomicAdd(&g_next, 1);
                if (idx >= TOTAL_STAGES) break;
                mbar_wait_parity(ebar0 + 8u * pslot, pphase);
                s_rowbase[pslot] = idx * ROWS_PER_STAGE;
                MBAR_EXPECT_TX(fbar0 + 8u * pslot, (uint32_t)STAGE_BYTES);   // release: orders s_rowbase
                BULK_G2S(smem_base + (uint32_t)pslot * STAGE_BYTES,
                         keys + (size_t)idx * ROWS_PER_STAGE * DIMK,
                         (uint32_t)STAGE_BYTES, fbar0 + 8u * pslot);
                if (++pslot == NSTAGES) { pslot = 0; pphase ^= 1u; }
            }
            // Sentinels: wake consumers once per slot with rowbase = -1
            #pragma unroll
            for (int j = 0; j < NSTAGES; j++) {
                mbar_wait_parity(ebar0 + 8u * pslot, pphase);
                s_rowbase[pslot] = -1;
                MBAR_ARRIVE(fbar0 + 8u * pslot);    // release-arrive flips full phase
                if (++pslot == NSTAGES) { pslot = 0; pphase ^= 1u; }
            }
        }
    } else {
        // ---------------- Consumer warps (free-running until sentinel) ----------------
        const float4* q4 = (const float4*)query;
        const float4 q0 = q4[lane];
        const float4 q1 = q4[lane + 32];
        const float4 q2 = q4[lane + 64];
        const float4 q3 = q4[lane + 96];

        float m = -CUDART_INF_F;
        float s = 0.0f;
        int   arg = 0;

        int cslot = 0;
        uint32_t cphase = 0;

        for (;;) {
            mbar_wait_parity(fbar0 + 8u * cslot, cphase);   // acquire: s_rowbase visible
            const int rowbase = s_rowbase[cslot];
            if (rowbase < 0) break;

            const int row = rowbase + wid;
            const float4* st = (const float4*)(stage_mem + (size_t)cslot * STAGE_BYTES
                                               + (size_t)wid * (DIMK * 4));
            float4 a  = st[lane];
            float4 bb = st[lane + 32];
            float4 c  = st[lane + 64];
            float4 d  = st[lane + 96];
            float acc;
            acc  = a.x * q0.x; acc = fmaf(a.y, q0.y, acc); acc = fmaf(a.z, q0.z, acc); acc = fmaf(a.w, q0.w, acc);
            acc  = fmaf(bb.x, q1.x, acc); acc = fmaf(bb.y, q1.y, acc); acc = fmaf(bb.z, q1.z, acc); acc = fmaf(bb.w, q1.w, acc);
            acc  = fmaf(c.x, q2.x, acc); acc = fmaf(c.y, q2.y, acc); acc = fmaf(c.z, q2.z, acc); acc = fmaf(c.w, q2.w, acc);
            acc  = fmaf(d.x, q3.x, acc); acc = fmaf(d.y, q3.y, acc); acc = fmaf(d.z, q3.z, acc); acc = fmaf(d.w, q3.w, acc);

            #pragma unroll
            for (int off = 16; off > 0; off >>= 1)
                acc += __shfl_xor_sync(0xffffffffu, acc, off);

            {
                float nm = fmaxf(m, acc);
                s = s * __expf(m - nm) + __expf(acc - nm);
                if (acc > m) arg = row;
                m = nm;
            }

            __syncwarp();
            if (lane == 0) MBAR_ARRIVE(ebar0 + 8u * cslot);   // warp done with slot

            if (++cslot == NSTAGES) { cslot = 0; cphase ^= 1u; }
        }

        if (lane == 0) {
            sm_m[wid] = m; sm_s[wid] = s; sm_a[wid] = arg;
        }
    }

    __syncthreads();

    // ---- Block-level merge of 16 consumer-warp partials ----
    if (tid == 0) {
        float bm = sm_m[0], bs = sm_s[0];
        int   ba = sm_a[0];
        #pragma unroll
        for (int w = 1; w < CONS_WARPS; w++)
            osm_merge(bm, bs, ba, sm_m[w], sm_s[w], sm_a[w]);
        g_bmax[b] = bm;
        g_bsum[b] = bs;
        g_barg[b] = ba;
        __threadfence();
        int old = atomicAdd(&g_ticket, 1);
        is_last = (old == BLOCKS - 1);
    }
    __syncthreads();

    if (!is_last) return;

    // ---- Last block: warp 0 merges 304 block partials (lean tail) ----
    if (wid == 0) {
        float lm = -CUDART_INF_F, ls = 0.0f;
        int   la = 0;
        #pragma unroll 1
        for (int i = lane; i < BLOCKS; i += 32)
            osm_merge(lm, ls, la, g_bmax[i], g_bsum[i], g_barg[i]);

        #pragma unroll
        for (int off = 16; off > 0; off >>= 1) {
            float m2 = __shfl_xor_sync(0xffffffffu, lm, off);
            float s2 = __shfl_xor_sync(0xffffffffu, ls, off);
            int   a2 = __shfl_xor_sync(0xffffffffu, la, off);
            float nm = fmaxf(lm, m2);
            ls = ls * __expf(lm - nm) + s2 * __expf(m2 - nm);
            if (m2 > lm) la = a2;
            lm = nm;
        }

        if (lane == 0) {
            s_best = la;
            s_inv  = 1.0f / ls;
            g_ticket = 0;   // reset for next graph replay
            g_next   = 0;   // reset steal cursor
        }
    }
    __syncthreads();

    if (tid < DIMV) {
        out[tid] = values[(size_t)s_best * DIMV + tid] * s_inv;
    }
}

extern "C" void kernel_launch(void* const* d_in, const int* in_sizes, int n_in,
                              void* d_out, int out_size) {
    const float* query  = (const float*)d_in[0];
    const float* keys   = (const float*)d_in[1];
    const float* values = (const float*)d_in[2];
    float* out = (float*)d_out;

    cudaFuncSetAttribute(fused_kernel,
                         cudaFuncAttributeMaxDynamicSharedMemorySize,
                         NSTAGES * STAGE_BYTES);
    fused_kernel<<<BLOCKS, TPB, NSTAGES * STAGE_BYTES>>>(keys, query, values, out);
}